// round 2
// baseline (speedup 1.0000x reference)
#include <cuda_runtime.h>

// Problem constants (fixed shapes from setup_inputs)
#define IMG_H 360
#define IMG_W 640
#define N_ROI 128
#define N_CH  196     // GROUP_C(4) * 7 * 7
#define PDIM  72      // patch dim with halo: roi <= 64 + 2 halo + slack
#define NPART 4       // row-split factor per channel
#define TPB   (224 * NPART)                 // 896 threads = 28 warps
#define SMEM_BYTES (3 * PDIM * PDIM * 4)    // 62208 B dynamic smem

// Fused: 3x3 SAME conv + bias + ReLU (on the fly per bin pixel)
//        -> ps_roi_pool (GROUP_C=4, 7x7) -> mean over 7x7 -> out [128,4]
// Each channel (g,ph,pw) is computed by NPART threads, each taking every
// NPART-th row of the bin rect; partials are reduced in smem.
__global__ __launch_bounds__(TPB, 1)
void fused_mv_psroi_kernel(const float* __restrict__ mv,     // [2,3,360,640]
                           const float* __restrict__ boxes,  // [128,5]
                           const float* __restrict__ msc,    // [1,2]
                           const float* __restrict__ cw,     // [196,3,3,3]
                           const float* __restrict__ cb,     // [196]
                           float* __restrict__ out)          // [128,4]
{
    extern __shared__ float patch[];         // [3][PDIM][PDIM]
    __shared__ float spool[NPART * N_CH];    // partial sums
    __shared__ float sbin[N_CH];             // per-channel pooled value

    const int k    = blockIdx.x;
    const int tid  = threadIdx.x;
    const int part = tid / 224;              // 0..3, warp-aligned (7 warps each)
    const int chan = tid - part * 224;       // 0..223, active if < 196

    // ---- box / bin geometry (uniform across threads) ----
    const float s  = __ldg(&msc[0]);
    const int   bi = (int)__ldg(&boxes[k * 5 + 0]);
    const float x1 = rintf(__ldg(&boxes[k * 5 + 1]) * s);   // jnp.round == rintf
    const float y1 = rintf(__ldg(&boxes[k * 5 + 2]) * s);
    const float x2 = rintf(__ldg(&boxes[k * 5 + 3]) * s);
    const float y2 = rintf(__ldg(&boxes[k * 5 + 4]) * s);

    const float roi_w = fmaxf(x2 - x1, 0.1f);
    const float roi_h = fmaxf(y2 - y1, 0.1f);
    const float bin_h = roi_h / 7.0f;
    const float bin_w = roi_w / 7.0f;

    // Whole-ROI extent (as the reference computes hs(0)..he(6), ws(0)..we(6))
    const int hs0 = min(max((int)floorf(y1), 0), IMG_H);
    const int he6 = min(max((int)ceilf(7.0f * bin_h + y1), 0), IMG_H);
    const int ws0 = min(max((int)floorf(x1), 0), IMG_W);
    const int we6 = min(max((int)ceilf(7.0f * bin_w + x1), 0), IMG_W);

    const int py0 = hs0 - 1;                 // patch origin incl. 1-px halo
    const int px0 = ws0 - 1;
    int PHt = min(max(he6 - hs0 + 2, 0), PDIM);
    int PWt = min(max(we6 - ws0 + 2, 0), PDIM);

    // ---- stage input patch into smem with zero halo (SAME padding) ----
    const int planesz = PHt * PWt;
    const int total   = 3 * planesz;
    const float* img  = mv + (size_t)bi * 3 * IMG_H * IMG_W;
    for (int i = tid; i < total; i += TPB) {
        const int ic = i / planesz;
        const int j  = i - ic * planesz;
        const int r  = j / PWt;
        const int cc = j - r * PWt;
        const int gy = py0 + r;
        const int gx = px0 + cc;
        float v = 0.0f;
        if ((unsigned)gy < IMG_H && (unsigned)gx < IMG_W)
            v = __ldg(&img[(ic * IMG_H + gy) * IMG_W + gx]);
        patch[(ic * PDIM + r) * PDIM + cc] = v;
    }
    __syncthreads();

    int area = 0;
    if (chan < N_CH) {
        const int g   = chan & 3;            // adjacent lanes share a bin rect
        const int bin = chan >> 2;
        const int ph  = bin / 7;
        const int pw  = bin % 7;
        const int c   = (g * 7 + ph) * 7 + pw;

        float wreg[27];
        #pragma unroll
        for (int j = 0; j < 27; j++) wreg[j] = __ldg(&cw[c * 27 + j]);
        const float bias = __ldg(&cb[c]);

        const float fph = (float)ph, fpw = (float)pw;
        const int hs = min(max((int)floorf(fph * bin_h + y1), 0), IMG_H);
        const int he = min(max((int)ceilf((fph + 1.0f) * bin_h + y1), 0), IMG_H);
        const int ws = min(max((int)floorf(fpw * bin_w + x1), 0), IMG_W);
        const int we = min(max((int)ceilf((fpw + 1.0f) * bin_w + x1), 0), IMG_W);
        area = (he - hs) * (we - ws);

        float sum = 0.0f;
        for (int yy = hs + part; yy < he; yy += NPART) {
            const int ry = yy - py0;         // rows ry-1..ry+1 valid (halo)
            // hoist the 9 row bases; 27 LDS per pixel, broadcast across 4 lanes
            const float* rb[9];
            #pragma unroll
            for (int ic = 0; ic < 3; ic++)
                #pragma unroll
                for (int ky = 0; ky < 3; ky++)
                    rb[ic * 3 + ky] = &patch[(ic * PDIM + (ry - 1 + ky)) * PDIM - px0];

            for (int xx = ws; xx < we; ++xx) {
                float v = bias;
                #pragma unroll
                for (int j = 0; j < 9; j++) {
                    const float* p = rb[j] + xx;
                    v = fmaf(p[-1], wreg[j * 3 + 0], v);
                    v = fmaf(p[ 0], wreg[j * 3 + 1], v);
                    v = fmaf(p[ 1], wreg[j * 3 + 2], v);
                }
                sum += fmaxf(v, 0.0f);       // ReLU then bin accumulation
            }
        }
        spool[part * N_CH + chan] = sum;
    }
    __syncthreads();

    // ---- combine partials, divide by area ----
    if (part == 0 && chan < N_CH) {
        float sfull = spool[chan] + spool[N_CH + chan]
                    + spool[2 * N_CH + chan] + spool[3 * N_CH + chan];
        sbin[chan] = (area > 0) ? (sfull / (float)area) : 0.0f;
    }
    __syncthreads();

    // ---- mean over the 49 bins of each group -> out[k,g] ----
    if (tid < 4) {
        float acc = 0.0f;
        #pragma unroll
        for (int b2 = 0; b2 < 49; b2++) acc += sbin[b2 * 4 + tid];
        out[k * 4 + tid] = acc / 49.0f;
    }
}

extern "C" void kernel_launch(void* const* d_in, const int* in_sizes, int n_in,
                              void* d_out, int out_size)
{
    const float* mv    = (const float*)d_in[0];  // motion_vectors [2,3,360,640]
    const float* boxes = (const float*)d_in[1];  // boxes_prev [128,5]
    const float* msc   = (const float*)d_in[2];  // motion_vector_scale [1,2]
    const float* cw    = (const float*)d_in[3];  // conv_w [196,3,3,3]
    const float* cb    = (const float*)d_in[4];  // conv_b [196]
    float* out         = (float*)d_out;          // [128,4]

    cudaFuncSetAttribute(fused_mv_psroi_kernel,
                         cudaFuncAttributeMaxDynamicSharedMemorySize, SMEM_BYTES);
    fused_mv_psroi_kernel<<<N_ROI, TPB, SMEM_BYTES>>>(mv, boxes, msc, cw, cb, out);
}

// round 4
// speedup vs baseline: 1.4106x; 1.4106x over previous
#include <cuda_runtime.h>
#include <cstdint>

// Problem constants (fixed shapes from setup_inputs)
#define IMG_H 360
#define IMG_W 640
#define N_ROI 128
#define N_CH  196     // GROUP_C(4) * 7 * 7
#define PDIM  72      // patch dim with halo
#define NPART 2       // row-split factor per channel
#define TPB   (224 * NPART)                 // 448 threads = 14 warps
#define SMEM_BYTES (3 * PDIM * PDIM * 4)    // 62208 B dynamic smem

__global__ __launch_bounds__(TPB, 1)
void fused_mv_psroi_kernel(const float* __restrict__ mv,     // [2,3,360,640]
                           const float* __restrict__ boxes,  // [128,5]
                           const float* __restrict__ msc,    // [1,2]
                           const float* __restrict__ cw,     // [196,3,3,3]
                           const float* __restrict__ cb,     // [196]
                           float* __restrict__ out)          // [128,4]
{
    extern __shared__ float patch[];         // [3][PDIM][PDIM]
    __shared__ float spool[NPART * N_CH];    // partial sums
    __shared__ float sbin[N_CH];             // pooled per-channel values

    const int k    = blockIdx.x;
    const int tid  = threadIdx.x;
    const int part = tid / 224;              // 0..NPART-1, warp-aligned
    const int chan = tid - part * 224;       // 0..223, active if < 196

    // ---- box / bin geometry (uniform) ----
    const float s  = __ldg(&msc[0]);
    const int   bi = (int)__ldg(&boxes[k * 5 + 0]);
    const float x1 = rintf(__ldg(&boxes[k * 5 + 1]) * s);   // jnp.round == rintf
    const float y1 = rintf(__ldg(&boxes[k * 5 + 2]) * s);
    const float x2 = rintf(__ldg(&boxes[k * 5 + 3]) * s);
    const float y2 = rintf(__ldg(&boxes[k * 5 + 4]) * s);

    const float roi_w = fmaxf(x2 - x1, 0.1f);
    const float roi_h = fmaxf(y2 - y1, 0.1f);
    const float bin_h = roi_h / 7.0f;
    const float bin_w = roi_w / 7.0f;

    const int hs0 = min(max((int)floorf(y1), 0), IMG_H);
    const int he6 = min(max((int)ceilf(7.0f * bin_h + y1), 0), IMG_H);
    const int ws0 = min(max((int)floorf(x1), 0), IMG_W);
    const int we6 = min(max((int)ceilf(7.0f * bin_w + x1), 0), IMG_W);

    const int py0 = hs0 - 1;                 // patch origin incl. 1-px halo
    const int px0 = ws0 - 1;
    const int PHt = min(max(he6 - hs0 + 2, 0), PDIM);
    const int PWt = min(max(we6 - ws0 + 2, 0), PDIM);

    // ---- phase A: zero patch (covers halo / OOB) ----
    {
        float4 z4 = make_float4(0.f, 0.f, 0.f, 0.f);
        float4* p4 = (float4*)patch;
        #pragma unroll 4
        for (int i = tid; i < 3 * PDIM * PDIM / 4; i += TPB) p4[i] = z4;
    }
    __syncthreads();

    // ---- phase B: cp.async the clipped in-bounds rectangle (no LDG->STS
    //      register round-trip, no per-element scoreboard serialization) ----
    {
        const int rlo = max(0, -py0);
        const int rhi = min(PHt, IMG_H - py0);
        const int clo = max(0, -px0);
        const int chi = min(PWt, IMG_W - px0);
        const int nr  = rhi - rlo;
        const int nc  = chi - clo;
        if (nr > 0 && nc > 0) {
            const int plane = nr * nc;
            const int tot   = 3 * plane;
            const float* img = mv + (size_t)bi * 3 * IMG_H * IMG_W;
            for (int i = tid; i < tot; i += TPB) {
                const int ic = i / plane;
                const int j  = i - ic * plane;
                const int r  = rlo + j / nc;
                const int cx = clo + (j - (j / nc) * nc);
                const float* gp = &img[(ic * IMG_H + (py0 + r)) * IMG_W + (px0 + cx)];
                uint32_t sa = (uint32_t)__cvta_generic_to_shared(
                                  &patch[(ic * PDIM + r) * PDIM + cx]);
                asm volatile("cp.async.ca.shared.global [%0], [%1], 4;\n"
                             :: "r"(sa), "l"(gp));
            }
        }
        asm volatile("cp.async.commit_group;\n" ::: "memory");
        asm volatile("cp.async.wait_group 0;\n" ::: "memory");
    }
    __syncthreads();

    int area = 0;
    if (chan < N_CH) {
        const int g   = chan & 3;            // 4 adjacent lanes share a bin rect
        const int bin = chan >> 2;
        const int ph  = bin / 7;
        const int pw  = bin % 7;
        const int c   = (g * 7 + ph) * 7 + pw;

        // weights split by kx for the rotating 3-column scheme
        float w0[9], w1[9], w2[9];
        #pragma unroll
        for (int j = 0; j < 9; j++) {
            w0[j] = __ldg(&cw[c * 27 + j * 3 + 0]);
            w1[j] = __ldg(&cw[c * 27 + j * 3 + 1]);
            w2[j] = __ldg(&cw[c * 27 + j * 3 + 2]);
        }
        const float bias = __ldg(&cb[c]);

        const float fph = (float)ph, fpw = (float)pw;
        const int hs = min(max((int)floorf(fph * bin_h + y1), 0), IMG_H);
        const int he = min(max((int)ceilf((fph + 1.0f) * bin_h + y1), 0), IMG_H);
        const int ws = min(max((int)floorf(fpw * bin_w + x1), 0), IMG_W);
        const int we = min(max((int)ceilf((fpw + 1.0f) * bin_w + x1), 0), IMG_W);
        area = (he - hs) * (we - ws);

        float sum = 0.0f;
        for (int yy = hs + part; yy < he; yy += NPART) {
            const int ry = yy - py0;          // rows ry-1..ry+1 valid (halo)
            // 9 row base offsets (ic,ky), pre-shifted so [xx] indexes image x
            int ro[9];
            #pragma unroll
            for (int ic = 0; ic < 3; ic++)
                #pragma unroll
                for (int ky = 0; ky < 3; ky++)
                    ro[ic * 3 + ky] = (ic * PDIM + (ry - 1 + ky)) * PDIM - px0;

            float a[9], b[9], cc[9];
            #pragma unroll
            for (int j = 0; j < 9; j++) {
                a[j] = patch[ro[j] + ws - 1];
                b[j] = patch[ro[j] + ws];
            }

            int xx = ws;
            while (xx < we) {
                {   // pixel xx: cols (a,b,new cc)
                    float v = bias;
                    #pragma unroll
                    for (int j = 0; j < 9; j++) cc[j] = patch[ro[j] + xx + 1];
                    #pragma unroll
                    for (int j = 0; j < 9; j++) v = fmaf(a[j], w0[j], v);
                    #pragma unroll
                    for (int j = 0; j < 9; j++) v = fmaf(b[j], w1[j], v);
                    #pragma unroll
                    for (int j = 0; j < 9; j++) v = fmaf(cc[j], w2[j], v);
                    sum += fmaxf(v, 0.0f);
                    ++xx;
                }
                if (xx >= we) break;
                {   // pixel xx: cols (b,cc,new a)
                    float v = bias;
                    #pragma unroll
                    for (int j = 0; j < 9; j++) a[j] = patch[ro[j] + xx + 1];
                    #pragma unroll
                    for (int j = 0; j < 9; j++) v = fmaf(b[j], w0[j], v);
                    #pragma unroll
                    for (int j = 0; j < 9; j++) v = fmaf(cc[j], w1[j], v);
                    #pragma unroll
                    for (int j = 0; j < 9; j++) v = fmaf(a[j], w2[j], v);
                    sum += fmaxf(v, 0.0f);
                    ++xx;
                }
                if (xx >= we) break;
                {   // pixel xx: cols (cc,a,new b)
                    float v = bias;
                    #pragma unroll
                    for (int j = 0; j < 9; j++) b[j] = patch[ro[j] + xx + 1];
                    #pragma unroll
                    for (int j = 0; j < 9; j++) v = fmaf(cc[j], w0[j], v);
                    #pragma unroll
                    for (int j = 0; j < 9; j++) v = fmaf(a[j], w1[j], v);
                    #pragma unroll
                    for (int j = 0; j < 9; j++) v = fmaf(b[j], w2[j], v);
                    sum += fmaxf(v, 0.0f);
                    ++xx;
                }
            }
        }
        spool[part * N_CH + chan] = sum;
    }
    __syncthreads();

    // ---- combine partials, divide by area ----
    if (part == 0 && chan < N_CH) {
        float sfull = 0.0f;
        #pragma unroll
        for (int p = 0; p < NPART; p++) sfull += spool[p * N_CH + chan];
        sbin[chan] = (area > 0) ? (sfull / (float)area) : 0.0f;
    }
    __syncthreads();

    // ---- mean over the 49 bins of each group -> out[k,g] ----
    if (tid < 4) {
        float acc = 0.0f;
        #pragma unroll
        for (int b2 = 0; b2 < 49; b2++) acc += sbin[b2 * 4 + tid];
        out[k * 4 + tid] = acc / 49.0f;
    }
}

extern "C" void kernel_launch(void* const* d_in, const int* in_sizes, int n_in,
                              void* d_out, int out_size)
{
    const float* mv    = (const float*)d_in[0];  // motion_vectors [2,3,360,640]
    const float* boxes = (const float*)d_in[1];  // boxes_prev [128,5]
    const float* msc   = (const float*)d_in[2];  // motion_vector_scale [1,2]
    const float* cw    = (const float*)d_in[3];  // conv_w [196,3,3,3]
    const float* cb    = (const float*)d_in[4];  // conv_b [196]
    float* out         = (float*)d_out;          // [128,4]

    cudaFuncSetAttribute(fused_mv_psroi_kernel,
                         cudaFuncAttributeMaxDynamicSharedMemorySize, SMEM_BYTES);
    fused_mv_psroi_kernel<<<N_ROI, TPB, SMEM_BYTES>>>(mv, boxes, msc, cw, cb, out);
}

// round 7
// speedup vs baseline: 1.4350x; 1.0173x over previous
#include <cuda_runtime.h>
#include <cstdint>

// Problem constants (fixed shapes from setup_inputs)
#define IMG_H 360
#define IMG_W 640
#define N_ROI 128
#define N_CH  196     // GROUP_C(4) * 7 * 7
#define PDIM  72      // patch dim with halo
#define NPART 2       // row-split factor per channel
#define TPB   (224 * NPART)                 // 448 threads = 14 warps
#define SMEM_BYTES (3 * PDIM * PDIM * 4)    // 62208 B dynamic smem

// One conv pixel: cols cL,cM already in regs; loads col (x+1) into cR.
// 3 independent accumulator chains (9 deep each) instead of one 27-deep.
__device__ __forceinline__ float conv_pixel(const float* __restrict__ patch,
                                            const int ro[9],
                                            float (&cL)[9], float (&cM)[9],
                                            float (&cR)[9],
                                            const float (&w0)[9],
                                            const float (&w1)[9],
                                            const float (&w2)[9],
                                            float bias, int x)
{
    #pragma unroll
    for (int j = 0; j < 9; j++) cR[j] = patch[ro[j] + x + 1];
    float v0 = bias, v1 = 0.0f, v2 = 0.0f;
    #pragma unroll
    for (int j = 0; j < 9; j++) {
        v0 = fmaf(cL[j], w0[j], v0);
        v1 = fmaf(cM[j], w1[j], v1);
        v2 = fmaf(cR[j], w2[j], v2);
    }
    return fmaxf(v0 + (v1 + v2), 0.0f);
}

__global__ __launch_bounds__(TPB, 1)
void fused_mv_psroi_kernel(const float* __restrict__ mv,     // [2,3,360,640]
                           const float* __restrict__ boxes,  // [128,5]
                           const float* __restrict__ msc,    // [1,2]
                           const float* __restrict__ cw,     // [196,3,3,3]
                           const float* __restrict__ cb,     // [196]
                           float* __restrict__ out)          // [128,4]
{
    extern __shared__ float patch[];         // [3][PDIM][PDIM]
    __shared__ float spool[NPART * N_CH];    // partial sums
    __shared__ float sbin[N_CH];             // pooled per-channel values

    const int k    = blockIdx.x;
    const int tid  = threadIdx.x;
    const int part = tid / 224;              // 0..NPART-1, warp-aligned
    const int chan = tid - part * 224;       // 0..223, active if < 196

    // ---- box / bin geometry (uniform) ----
    const float s  = __ldg(&msc[0]);
    const int   bi = (int)__ldg(&boxes[k * 5 + 0]);
    const float x1 = rintf(__ldg(&boxes[k * 5 + 1]) * s);   // jnp.round == rintf
    const float y1 = rintf(__ldg(&boxes[k * 5 + 2]) * s);
    const float x2 = rintf(__ldg(&boxes[k * 5 + 3]) * s);
    const float y2 = rintf(__ldg(&boxes[k * 5 + 4]) * s);

    const float roi_w = fmaxf(x2 - x1, 0.1f);
    const float roi_h = fmaxf(y2 - y1, 0.1f);
    const float bin_h = roi_h / 7.0f;
    const float bin_w = roi_w / 7.0f;

    const int hs0 = min(max((int)floorf(y1), 0), IMG_H);
    const int he6 = min(max((int)ceilf(7.0f * bin_h + y1), 0), IMG_H);
    const int ws0 = min(max((int)floorf(x1), 0), IMG_W);
    const int we6 = min(max((int)ceilf(7.0f * bin_w + x1), 0), IMG_W);

    const int py0 = hs0 - 1;                 // patch origin incl. 1-px halo
    const int px0 = ws0 - 1;
    const int PHt = min(max(he6 - hs0 + 2, 0), PDIM);
    const int PWt = min(max(we6 - ws0 + 2, 0), PDIM);

    // ---- phase A: zero patch (covers halo / OOB) ----
    {
        float4 z4 = make_float4(0.f, 0.f, 0.f, 0.f);
        float4* p4 = (float4*)patch;
        #pragma unroll 4
        for (int i = tid; i < 3 * PDIM * PDIM / 4; i += TPB) p4[i] = z4;
    }
    __syncthreads();

    // ---- phase B: cp.async the clipped in-bounds rectangle ----
    {
        const int rlo = max(0, -py0);
        const int rhi = min(PHt, IMG_H - py0);
        const int clo = max(0, -px0);
        const int chi = min(PWt, IMG_W - px0);
        const int nr  = rhi - rlo;
        const int nc  = chi - clo;
        if (nr > 0 && nc > 0) {
            const int plane = nr * nc;
            const int tot   = 3 * plane;
            const float* img = mv + (size_t)bi * 3 * IMG_H * IMG_W;
            for (int i = tid; i < tot; i += TPB) {
                const int ic = i / plane;
                const int j  = i - ic * plane;
                const int r  = rlo + j / nc;
                const int cx = clo + (j - (j / nc) * nc);
                const float* gp = &img[(ic * IMG_H + (py0 + r)) * IMG_W + (px0 + cx)];
                uint32_t sa = (uint32_t)__cvta_generic_to_shared(
                                  &patch[(ic * PDIM + r) * PDIM + cx]);
                asm volatile("cp.async.ca.shared.global [%0], [%1], 4;\n"
                             :: "r"(sa), "l"(gp));
            }
        }
        asm volatile("cp.async.commit_group;\n" ::: "memory");
        asm volatile("cp.async.wait_group 0;\n" ::: "memory");
    }
    __syncthreads();

    int area = 0;
    if (chan < N_CH) {
        const int g   = chan & 3;            // 4 adjacent lanes share a bin rect
        const int bin = chan >> 2;
        const int ph  = bin / 7;
        const int pw  = bin % 7;
        const int c   = (g * 7 + ph) * 7 + pw;

        // weights split by kx for the rotating 3-column scheme
        float w0[9], w1[9], w2[9];
        #pragma unroll
        for (int j = 0; j < 9; j++) {
            w0[j] = __ldg(&cw[c * 27 + j * 3 + 0]);
            w1[j] = __ldg(&cw[c * 27 + j * 3 + 1]);
            w2[j] = __ldg(&cw[c * 27 + j * 3 + 2]);
        }
        const float bias = __ldg(&cb[c]);

        const float fph = (float)ph, fpw = (float)pw;
        const int hs = min(max((int)floorf(fph * bin_h + y1), 0), IMG_H);
        const int he = min(max((int)ceilf((fph + 1.0f) * bin_h + y1), 0), IMG_H);
        const int ws = min(max((int)floorf(fpw * bin_w + x1), 0), IMG_W);
        const int we = min(max((int)ceilf((fpw + 1.0f) * bin_w + x1), 0), IMG_W);
        area = (he - hs) * (we - ws);

        const int npx = we - ws;
        const int n3  = npx > 0 ? npx / 3 : 0;
        const int rem = npx > 0 ? npx - 3 * n3 : 0;

        float sum = 0.0f;
        for (int yy = hs + part; yy < he; yy += NPART) {
            const int ry = yy - py0;          // rows ry-1..ry+1 valid (halo)
            int ro[9];
            #pragma unroll
            for (int ic = 0; ic < 3; ic++)
                #pragma unroll
                for (int ky = 0; ky < 3; ky++)
                    ro[ic * 3 + ky] = (ic * PDIM + (ry - 1 + ky)) * PDIM - px0;

            float a[9], b[9], cc[9];
            #pragma unroll
            for (int j = 0; j < 9; j++) {
                a[j] = patch[ro[j] + ws - 1];
                b[j] = patch[ro[j] + ws];
            }

            int xx = ws;
            // branch-free main body: 3 pixels per iter, full register rotation
            for (int t = 0; t < n3; ++t) {
                sum += conv_pixel(patch, ro, a,  b,  cc, w0, w1, w2, bias, xx);
                sum += conv_pixel(patch, ro, b,  cc, a,  w0, w1, w2, bias, xx + 1);
                sum += conv_pixel(patch, ro, cc, a,  b,  w0, w1, w2, bias, xx + 2);
                xx += 3;
            }
            if (rem >= 1)
                sum += conv_pixel(patch, ro, a, b, cc, w0, w1, w2, bias, xx);
            if (rem == 2)
                sum += conv_pixel(patch, ro, b, cc, a, w0, w1, w2, bias, xx + 1);
        }
        spool[part * N_CH + chan] = sum;
    }
    __syncthreads();

    // ---- combine partials, divide by area ----
    if (part == 0 && chan < N_CH) {
        float sfull = 0.0f;
        #pragma unroll
        for (int p = 0; p < NPART; p++) sfull += spool[p * N_CH + chan];
        sbin[chan] = (area > 0) ? (sfull / (float)area) : 0.0f;
    }
    __syncthreads();

    // ---- mean over the 49 bins of each group -> out[k,g] ----
    if (tid < 4) {
        float acc = 0.0f;
        #pragma unroll
        for (int b2 = 0; b2 < 49; b2++) acc += sbin[b2 * 4 + tid];
        out[k * 4 + tid] = acc / 49.0f;
    }
}

extern "C" void kernel_launch(void* const* d_in, const int* in_sizes, int n_in,
                              void* d_out, int out_size)
{
    const float* mv    = (const float*)d_in[0];  // motion_vectors [2,3,360,640]
    const float* boxes = (const float*)d_in[1];  // boxes_prev [128,5]
    const float* msc   = (const float*)d_in[2];  // motion_vector_scale [1,2]
    const float* cw    = (const float*)d_in[3];  // conv_w [196,3,3,3]
    const float* cb    = (const float*)d_in[4];  // conv_b [196]
    float* out         = (float*)d_out;          // [128,4]

    cudaFuncSetAttribute(fused_mv_psroi_kernel,
                         cudaFuncAttributeMaxDynamicSharedMemorySize, SMEM_BYTES);
    fused_mv_psroi_kernel<<<N_ROI, TPB, SMEM_BYTES>>>(mv, boxes, msc, cw, cb, out);
}